// round 1
// baseline (speedup 1.0000x reference)
#include <cuda_runtime.h>
#include <cuda_bf16.h>
#include <limits.h>

// Problem constants (fixed shapes per reference)
#define BATCH   8
#define CDIM    64
#define GDIM    65536
#define NLAYER  4
#define TPB     128
#define SLOPE   0.1f

// Scratch (allocation-free rule: __device__ globals)
__device__ float g_WT[NLAYER][64][64];      // effective weights, transposed: [l][c][o]
__device__ float g_bias[NLAYER][BATCH][64]; // per-batch per-layer bias
__device__ int   g_maxkey[BATCH * 64];      // monotone-int-keyed running max

// Monotone int key for float max via atomicMax (order-independent, exact)
__device__ __forceinline__ int f2key(float f) {
    int b = __float_as_int(f);
    return b >= 0 ? b : (b ^ 0x7fffffff);
}
__device__ __forceinline__ float key2f(int k) {
    return __int_as_float(k >= 0 ? k : (k ^ 0x7fffffff));
}

__device__ __forceinline__ float lrelu(float a) {
    // a>=0 -> a ; a<0 -> 0.1*a. fmaxf picks correctly for both signs.
    return fmaxf(a, SLOPE * a);
}

// ---------------------------------------------------------------------------
// Kernel 0: reset running-max keys every call (graph-replay deterministic)
// ---------------------------------------------------------------------------
__global__ void init_kernel() {
    int i = blockIdx.x * blockDim.x + threadIdx.x;
    if (i < BATCH * 64) g_maxkey[i] = INT_MIN;
}

// ---------------------------------------------------------------------------
// Kernel 1: precompute Weff^T and the per-layer/per-batch bias chain.
//   Weff = W[:, :64] + W[:, 64:]
//   x0_0[b]     = features[b, :, 0]
//   bias_l[b]   = -W_l[:, 64:] @ x0_l[b]
//   x0_{l+1}[b] = lrelu(W_l[:, :64] @ x0_l[b])
// Single block, tiny.
// ---------------------------------------------------------------------------
__global__ void setup_kernel(const float* __restrict__ feat,
                             const float* __restrict__ W0,
                             const float* __restrict__ W1,
                             const float* __restrict__ W2,
                             const float* __restrict__ W3) {
    const float* Ws[NLAYER] = {W0, W1, W2, W3};
    const int tid = threadIdx.x;  // 256 threads

    // Effective transposed weights
    #pragma unroll 1
    for (int l = 0; l < NLAYER; l++) {
        const float* W = Ws[l];
        for (int i = tid; i < 64 * 64; i += 256) {
            int o = i >> 6, c = i & 63;
            g_WT[l][c][o] = W[o * 128 + c] + W[o * 128 + 64 + c];
        }
    }

    __shared__ float sx0[BATCH][64];
    __shared__ float sy[BATCH][64];
    for (int i = tid; i < BATCH * 64; i += 256) {
        int b = i >> 6, c = i & 63;
        sx0[b][c] = feat[(size_t)b * CDIM * GDIM + (size_t)c * GDIM];  // g = 0
    }
    __syncthreads();

    #pragma unroll 1
    for (int l = 0; l < NLAYER; l++) {
        const float* W = Ws[l];
        for (int i = tid; i < BATCH * 64; i += 256) {
            int b = i >> 6, o = i & 63;
            float da = 0.0f, db = 0.0f;
            #pragma unroll
            for (int c = 0; c < 64; c++) {
                float xv = sx0[b][c];
                da = fmaf(W[o * 128 + c],      xv, da);
                db = fmaf(W[o * 128 + 64 + c], xv, db);
            }
            g_bias[l][b][o] = -db;
            sy[b][o] = lrelu(da);
        }
        __syncthreads();
        for (int i = tid; i < BATCH * 64; i += 256) (&sx0[0][0])[i] = (&sy[0][0])[i];
        __syncthreads();
    }
}

// ---------------------------------------------------------------------------
// Kernel 2: main fused 4-layer MLP per column + block max-reduce.
// One thread per column g. x/y fully register-resident (all loops unrolled).
// Weights broadcast from smem (transposed -> one float4 LDS feeds 4 accs).
// ---------------------------------------------------------------------------
__global__ void __launch_bounds__(TPB)
main_kernel(const float* __restrict__ feat) {
    const int b   = blockIdx.y;
    const int g   = blockIdx.x * TPB + threadIdx.x;
    const int tid = threadIdx.x;

    __shared__ float sW[64 * 64];   // [c][o]
    __shared__ float sbias[64];
    __shared__ int   smax[64];

    // Load column (coalesced across warp for each c)
    float x[64];
    const float* fb = feat + (size_t)b * CDIM * GDIM + g;
    #pragma unroll
    for (int c = 0; c < 64; c++) x[c] = fb[(size_t)c * GDIM];

    #pragma unroll 1
    for (int l = 0; l < NLAYER; l++) {
        __syncthreads();  // previous layer's smem reads complete
        const float* wsrc = &g_WT[l][0][0];
        for (int i = tid; i < 64 * 64; i += TPB) sW[i] = wsrc[i];
        if (tid < 64) sbias[tid] = g_bias[l][b][tid];
        __syncthreads();

        float y[64];
        #pragma unroll
        for (int o = 0; o < 64; o += 4) {
            float a0 = sbias[o + 0];
            float a1 = sbias[o + 1];
            float a2 = sbias[o + 2];
            float a3 = sbias[o + 3];
            #pragma unroll
            for (int c = 0; c < 64; c++) {
                const float4 w = *reinterpret_cast<const float4*>(&sW[c * 64 + o]);
                const float xv = x[c];
                a0 = fmaf(w.x, xv, a0);
                a1 = fmaf(w.y, xv, a1);
                a2 = fmaf(w.z, xv, a2);
                a3 = fmaf(w.w, xv, a3);
            }
            y[o + 0] = lrelu(a0);
            y[o + 1] = lrelu(a1);
            y[o + 2] = lrelu(a2);
            y[o + 3] = lrelu(a3);
        }
        #pragma unroll
        for (int c = 0; c < 64; c++) x[c] = y[c];
    }

    // Block-level max per output channel
    if (tid < 64) smax[tid] = INT_MIN;
    __syncthreads();
    #pragma unroll
    for (int o = 0; o < 64; o++) {
        float v = x[o];
        #pragma unroll
        for (int d = 16; d > 0; d >>= 1)
            v = fmaxf(v, __shfl_xor_sync(0xffffffffu, v, d));
        if ((tid & 31) == 0) atomicMax(&smax[o], f2key(v));
    }
    __syncthreads();
    if (tid < 64) atomicMax(&g_maxkey[b * 64 + tid], smax[tid]);
}

// ---------------------------------------------------------------------------
// Kernel 3: convert keys to floats into d_out [B, 64]
// ---------------------------------------------------------------------------
__global__ void fin_kernel(float* __restrict__ out) {
    int i = blockIdx.x * blockDim.x + threadIdx.x;
    if (i < BATCH * 64) out[i] = key2f(g_maxkey[i]);
}

// ---------------------------------------------------------------------------
extern "C" void kernel_launch(void* const* d_in, const int* in_sizes, int n_in,
                              void* d_out, int out_size) {
    const float* feat = (const float*)d_in[0];
    const float* W0   = (const float*)d_in[1];
    const float* W1   = (const float*)d_in[2];
    const float* W2   = (const float*)d_in[3];
    const float* W3   = (const float*)d_in[4];
    float* out = (float*)d_out;

    init_kernel<<<2, 256>>>();
    setup_kernel<<<1, 256>>>(feat, W0, W1, W2, W3);
    dim3 grid(GDIM / TPB, BATCH);
    main_kernel<<<grid, TPB>>>(feat);
    fin_kernel<<<2, 256>>>(out);
}

// round 3
// speedup vs baseline: 2.7714x; 2.7714x over previous
#include <cuda_runtime.h>
#include <cuda_bf16.h>
#include <cstdint>
#include <limits.h>

// ---------------- problem constants ----------------
#define BATCH   8
#define CDIM    64
#define GDIM    65536
#define NLAYER  4
#define SLOPE   0.1f

#define TPB     256
#define GRID    296                         // 2 CTAs/SM x 148
#define WARPS_PER_CTA (TPB / 32)
#define NWTILES (GDIM * BATCH / 16)         // 32768 warp-tiles of 16 columns

// smem layout (dynamic)
#define SMB_BYTES   (4 * 8 * 8 * 32 * 8)    // B fragments: 65536
#define SMBIAS_OFF  SMB_BYTES               // 8 batches x 4 layers x 64 fp32 = 8192
#define SMMAX_OFF   (SMBIAS_OFF + 8192)     // 8 x 64 int = 2048
#define SM_TOTAL    (SMMAX_OFF + 2048)

// ---------------- helpers ----------------
// cvt.rn.bf16x2.f32 d, a, b -> d.hi = cvt(a), d.lo = cvt(b).
// CVT_BF16X2(res, a, b): res.lo = bf16(a), res.hi = bf16(b)
#define CVT_BF16X2(res, a, b) \
    asm("cvt.rn.bf16x2.f32 %0, %1, %2;" : "=r"(res) : "f"(b), "f"(a))

__device__ __forceinline__ void split2(float a, float b, uint32_t& h, uint32_t& l) {
    uint32_t ph; CVT_BF16X2(ph, a, b);
    float ha = __uint_as_float(ph << 16);
    float hb = __uint_as_float(ph & 0xffff0000u);
    uint32_t pl; CVT_BF16X2(pl, a - ha, b - hb);
    h = ph; l = pl;
}

#define MMA16816(d, a0, a1, a2, a3, b0, b1) \
    asm volatile("mma.sync.aligned.m16n8k16.row.col.f32.bf16.bf16.f32 " \
        "{%0,%1,%2,%3}, {%4,%5,%6,%7}, {%8,%9}, {%0,%1,%2,%3};" \
        : "+f"((d)[0]), "+f"((d)[1]), "+f"((d)[2]), "+f"((d)[3]) \
        : "r"(a0), "r"(a1), "r"(a2), "r"(a3), "r"(b0), "r"(b1))

__device__ __forceinline__ int f2key(float f) {
    int b = __float_as_int(f);
    return b >= 0 ? b : (b ^ 0x7fffffff);
}
__device__ __forceinline__ float key2f(int k) {
    return __int_as_float(k >= 0 ? k : (k ^ 0x7fffffff));
}
__device__ __forceinline__ float lrelu(float a) { return fmaxf(a, SLOPE * a); }

// ---------------- device globals ----------------
__device__ float g_bias[NLAYER][BATCH][64];
__device__ int   g_maxkey[BATCH * 64];

// ---------------- kernel 0: reset running max ----------------
__global__ void init_kernel() {
    int i = blockIdx.x * blockDim.x + threadIdx.x;
    if (i < BATCH * 64) g_maxkey[i] = INT_MIN;
}

// ---------------- kernel 1: bias chain (exact fp32, tiny) ----------------
__global__ void setup_kernel(const float* __restrict__ feat,
                             const float* __restrict__ W0,
                             const float* __restrict__ W1,
                             const float* __restrict__ W2,
                             const float* __restrict__ W3) {
    const float* Ws[NLAYER] = {W0, W1, W2, W3};
    const int tid = threadIdx.x;  // 256
    __shared__ float sx0[BATCH][64];
    __shared__ float sy[BATCH][64];
    for (int i = tid; i < BATCH * 64; i += 256) {
        int b = i >> 6, c = i & 63;
        sx0[b][c] = feat[(size_t)b * CDIM * GDIM + (size_t)c * GDIM];
    }
    __syncthreads();
    #pragma unroll 1
    for (int l = 0; l < NLAYER; l++) {
        const float* W = Ws[l];
        for (int i = tid; i < BATCH * 64; i += 256) {
            int b = i >> 6, o = i & 63;
            float da = 0.f, db = 0.f;
            #pragma unroll
            for (int c = 0; c < 64; c++) {
                float xv = sx0[b][c];
                da = fmaf(W[o * 128 + c], xv, da);
                db = fmaf(W[o * 128 + 64 + c], xv, db);
            }
            g_bias[l][b][o] = -db;
            sy[b][o] = lrelu(da);
        }
        __syncthreads();
        for (int i = tid; i < BATCH * 64; i += 256) (&sx0[0][0])[i] = (&sy[0][0])[i];
        __syncthreads();
    }
}

// ---------------- kernel 2: persistent mma.sync MLP ----------------
// Warp-tile = 16 columns. A fragments (X split hi/lo) register-resident;
// D fragment of layer l IS the A fragment of layer l+1 (no shuffles).
__global__ void __launch_bounds__(TPB, 2)
mlp_kernel(const float* __restrict__ feat,
           const float* __restrict__ W0, const float* __restrict__ W1,
           const float* __restrict__ W2, const float* __restrict__ W3) {
    extern __shared__ char smem[];
    uint2* sB    = (uint2*)smem;                    // [l][sb][j][lane] 8B each
    float* sbias = (float*)(smem + SMBIAS_OFF);     // [b][l][o]
    int*   smax  = (int*)(smem + SMMAX_OFF);        // [b][o]

    const int tid  = threadIdx.x;
    const int wid  = tid >> 5;
    const int lane = tid & 31;
    const int g    = lane >> 2;   // group (row within fragment)
    const int t    = lane & 3;    // thread-in-group

    // ---- prologue: pack B fragments (Weff hi/lo) into smem ----
    {
        const float* Ws[NLAYER] = {W0, W1, W2, W3};
        for (int idx = tid; idx < 4 * 8 * 8 * 32; idx += TPB) {
            int ln = idx & 31, j = (idx >> 5) & 7, sb = (idx >> 8) & 7, l = idx >> 11;
            int gg = ln >> 2, tt = ln & 3;
            int o = 8 * j + gg;
            int cb = 16 * (sb & 3) + 2 * tt;
            const float* W = Ws[l] + o * 128;
            float v0 = W[cb]     + W[64 + cb];
            float v1 = W[cb + 1] + W[64 + cb + 1];
            float v8 = W[cb + 8] + W[64 + cb + 8];
            float v9 = W[cb + 9] + W[64 + cb + 9];
            uint32_t h01, l01, h89, l89;
            split2(v0, v1, h01, l01);
            split2(v8, v9, h89, l89);
            sB[idx] = (sb < 4) ? make_uint2(h01, h89) : make_uint2(l01, l89);
        }
        for (int idx = tid; idx < BATCH * NLAYER * 64; idx += TPB) {
            int b = idx >> 8, l = (idx >> 6) & 3, o = idx & 63;
            sbias[idx] = g_bias[l][b][o];
        }
        for (int idx = tid; idx < BATCH * 64; idx += TPB) smax[idx] = INT_MIN;
    }
    __syncthreads();

    const int wglobal = blockIdx.x * WARPS_PER_CTA + wid;
    const int wstride = gridDim.x * WARPS_PER_CTA;

    for (int tt_idx = wglobal; tt_idx < NWTILES; tt_idx += wstride) {
        const int b  = tt_idx >> 12;           // 4096 tiles per batch
        const int g0 = (tt_idx & 4095) << 4;   // 16 columns per tile

        // ---- load X tile, split to bf16 hi/lo A fragments ----
        uint32_t Ah[16], Al[16];
        {
            const float* fp = feat + (size_t)b * CDIM * GDIM + g0 + g;
            #pragma unroll
            for (int s = 0; s < 4; s++) {
                int cb = 16 * s + 2 * t;
                float x0 = __ldg(fp + (size_t)cb * GDIM);
                float x1 = __ldg(fp + (size_t)(cb + 1) * GDIM);
                split2(x0, x1, Ah[4 * s + 0], Al[4 * s + 0]);
                float x2 = __ldg(fp + (size_t)cb * GDIM + 8);
                float x3 = __ldg(fp + (size_t)(cb + 1) * GDIM + 8);
                split2(x2, x3, Ah[4 * s + 1], Al[4 * s + 1]);
                float x4 = __ldg(fp + (size_t)(cb + 8) * GDIM);
                float x5 = __ldg(fp + (size_t)(cb + 9) * GDIM);
                split2(x4, x5, Ah[4 * s + 2], Al[4 * s + 2]);
                float x6 = __ldg(fp + (size_t)(cb + 8) * GDIM + 8);
                float x7 = __ldg(fp + (size_t)(cb + 9) * GDIM + 8);
                split2(x6, x7, Ah[4 * s + 3], Al[4 * s + 3]);
            }
        }

        #pragma unroll 1
        for (int l = 0; l < NLAYER; l++) {
            float Dm[8][4];
            // init accumulators with bias
            const float2* bp = (const float2*)(sbias + (b * 4 + l) * 64);
            #pragma unroll
            for (int j = 0; j < 8; j++) {
                float2 bv = bp[4 * j + t];
                Dm[j][0] = bv.x; Dm[j][1] = bv.y;
                Dm[j][2] = bv.x; Dm[j][3] = bv.y;
            }
            // K = 192: s 0-3 Xh*Wh, 4-7 Xl*Wh, 8-11 Xh*Wl
            const uint2* Bl = sB + l * (8 * 8 * 32) + lane;
            #pragma unroll
            for (int s = 0; s < 12; s++) {
                const int sb = (s < 4) ? s : (s - 4);
                const uint32_t* Aa = (s >= 4 && s < 8) ? (Al + 4 * (s & 3))
                                                       : (Ah + 4 * (s & 3));
                #pragma unroll
                for (int j = 0; j < 8; j++) {
                    uint2 bf = Bl[(sb * 8 + j) * 32];
                    MMA16816(Dm[j], Aa[0], Aa[1], Aa[2], Aa[3], bf.x, bf.y);
                }
            }

            if (l < NLAYER - 1) {
                // epilogue: lrelu + split; D fragment j -> A fragment pieces
                #pragma unroll
                for (int j = 0; j < 8; j++) {
                    float y0 = lrelu(Dm[j][0]);
                    float y1 = lrelu(Dm[j][1]);
                    float y2 = lrelu(Dm[j][2]);
                    float y3 = lrelu(Dm[j][3]);
                    uint32_t h01, l01, h23, l23;
                    split2(y0, y1, h01, l01);   // row r
                    split2(y2, y3, h23, l23);   // row r+8
                    const int s = j >> 1;
                    if ((j & 1) == 0) {
                        Ah[4 * s + 0] = h01; Al[4 * s + 0] = l01;
                        Ah[4 * s + 1] = h23; Al[4 * s + 1] = l23;
                    } else {
                        Ah[4 * s + 2] = h01; Al[4 * s + 2] = l01;
                        Ah[4 * s + 3] = h23; Al[4 * s + 3] = l23;
                    }
                }
            } else {
                // final layer: max over the 16 rows, then smem atomics
                int* sm = smax + b * 64;
                #pragma unroll
                for (int j = 0; j < 8; j++) {
                    float m0 = fmaxf(lrelu(Dm[j][0]), lrelu(Dm[j][2]));
                    float m1 = fmaxf(lrelu(Dm[j][1]), lrelu(Dm[j][3]));
                    m0 = fmaxf(m0, __shfl_xor_sync(0xffffffffu, m0, 4));
                    m0 = fmaxf(m0, __shfl_xor_sync(0xffffffffu, m0, 8));
                    m0 = fmaxf(m0, __shfl_xor_sync(0xffffffffu, m0, 16));
                    m1 = fmaxf(m1, __shfl_xor_sync(0xffffffffu, m1, 4));
                    m1 = fmaxf(m1, __shfl_xor_sync(0xffffffffu, m1, 8));
                    m1 = fmaxf(m1, __shfl_xor_sync(0xffffffffu, m1, 16));
                    if (lane < 4) {
                        atomicMax(&sm[8 * j + 2 * t],     f2key(m0));
                        atomicMax(&sm[8 * j + 2 * t + 1], f2key(m1));
                    }
                }
            }
        }
    }

    __syncthreads();
    for (int idx = tid; idx < BATCH * 64; idx += TPB)
        atomicMax(&g_maxkey[idx], smax[idx]);
}

// ---------------- kernel 3: output ----------------
__global__ void fin_kernel(float* __restrict__ out) {
    int i = blockIdx.x * blockDim.x + threadIdx.x;
    if (i < BATCH * 64) out[i] = key2f(g_maxkey[i]);
}

// ---------------------------------------------------------------------------
extern "C" void kernel_launch(void* const* d_in, const int* in_sizes, int n_in,
                              void* d_out, int out_size) {
    const float* feat = (const float*)d_in[0];
    const float* W0   = (const float*)d_in[1];
    const float* W1   = (const float*)d_in[2];
    const float* W2   = (const float*)d_in[3];
    const float* W3   = (const float*)d_in[4];
    float* out = (float*)d_out;

    cudaFuncSetAttribute(mlp_kernel, cudaFuncAttributeMaxDynamicSharedMemorySize, SM_TOTAL);

    init_kernel<<<2, 256>>>();
    setup_kernel<<<1, 256>>>(feat, W0, W1, W2, W3);
    mlp_kernel<<<GRID, TPB, SM_TOTAL>>>(feat, W0, W1, W2, W3);
    fin_kernel<<<2, 256>>>(out);
}

// round 4
// speedup vs baseline: 3.1916x; 1.1516x over previous
#include <cuda_runtime.h>
#include <cuda_fp16.h>
#include <cstdint>
#include <limits.h>

// ---------------- problem constants ----------------
#define BATCH   8
#define CDIM    64
#define GDIM    65536
#define NLAYER  4
#define SLOPE   0.1f

#define TPB     256
#define GRID    296                         // 2 CTAs/SM x 148
#define WARPS_PER_CTA (TPB / 32)
#define NWTILES (GDIM * BATCH / 16)         // 32768 warp-tiles of 16 columns

// smem layout (dynamic)
#define SMB_BYTES   (4 * 4 * 8 * 32 * 8)    // B fragments (Wh only): 32768
#define SMBIAS_OFF  SMB_BYTES               // 8 batches x 4 layers x 64 fp32 = 8192
#define SMMAX_OFF   (SMBIAS_OFF + 8192)     // 8 x 64 int = 2048
#define SM_TOTAL    (SMMAX_OFF + 2048)

// ---------------- helpers ----------------
// fp16 hi/lo split: h = f16x2(a,b) (lo=a, hi=b); l = f16x2 of residuals.
__device__ __forceinline__ void split2h(float a, float b, uint32_t& h, uint32_t& l) {
    uint32_t ph;
    asm("cvt.rn.f16x2.f32 %0, %1, %2;" : "=r"(ph) : "f"(b), "f"(a));
    float ha, hb;
    asm("{\n\t.reg .b16 x, y;\n\tmov.b32 {x, y}, %2;\n\t"
        "cvt.f32.f16 %0, x;\n\tcvt.f32.f16 %1, y;\n\t}"
        : "=f"(ha), "=f"(hb) : "r"(ph));
    uint32_t pl;
    asm("cvt.rn.f16x2.f32 %0, %1, %2;" : "=r"(pl) : "f"(b - hb), "f"(a - ha));
    h = ph; l = pl;
}

#define MMA16816(d, a0, a1, a2, a3, b0, b1) \
    asm volatile("mma.sync.aligned.m16n8k16.row.col.f32.f16.f16.f32 " \
        "{%0,%1,%2,%3}, {%4,%5,%6,%7}, {%8,%9}, {%0,%1,%2,%3};" \
        : "+f"((d)[0]), "+f"((d)[1]), "+f"((d)[2]), "+f"((d)[3]) \
        : "r"(a0), "r"(a1), "r"(a2), "r"(a3), "r"(b0), "r"(b1))

__device__ __forceinline__ int f2key(float f) {
    int b = __float_as_int(f);
    return b >= 0 ? b : (b ^ 0x7fffffff);
}
__device__ __forceinline__ float key2f(int k) {
    return __int_as_float(k >= 0 ? k : (k ^ 0x7fffffff));
}
__device__ __forceinline__ float lrelu(float a) { return fmaxf(a, SLOPE * a); }

// ---------------- device globals ----------------
__device__ float g_bias[NLAYER][BATCH][64];
__device__ int   g_maxkey[BATCH * 64];

// ---------------- kernel 0: reset running max ----------------
__global__ void init_kernel() {
    int i = blockIdx.x * blockDim.x + threadIdx.x;
    if (i < BATCH * 64) g_maxkey[i] = INT_MIN;
}

// no-op padding so ncu's "-s 5 -c 1" lands on mlp_kernel (launch index 5)
__global__ void dummy_kernel() {}

// ---------------- kernel 1: bias chain (exact fp32, tiny) ----------------
__global__ void setup_kernel(const float* __restrict__ feat,
                             const float* __restrict__ W0,
                             const float* __restrict__ W1,
                             const float* __restrict__ W2,
                             const float* __restrict__ W3) {
    const float* Ws[NLAYER] = {W0, W1, W2, W3};
    const int tid = threadIdx.x;  // 256
    __shared__ float sx0[BATCH][64];
    __shared__ float sy[BATCH][64];
    for (int i = tid; i < BATCH * 64; i += 256) {
        int b = i >> 6, c = i & 63;
        sx0[b][c] = feat[(size_t)b * CDIM * GDIM + (size_t)c * GDIM];
    }
    __syncthreads();
    #pragma unroll 1
    for (int l = 0; l < NLAYER; l++) {
        const float* W = Ws[l];
        for (int i = tid; i < BATCH * 64; i += 256) {
            int b = i >> 6, o = i & 63;
            float da = 0.f, db = 0.f;
            #pragma unroll
            for (int c = 0; c < 64; c++) {
                float xv = sx0[b][c];
                da = fmaf(W[o * 128 + c], xv, da);
                db = fmaf(W[o * 128 + 64 + c], xv, db);
            }
            g_bias[l][b][o] = -db;
            sy[b][o] = lrelu(da);
        }
        __syncthreads();
        for (int i = tid; i < BATCH * 64; i += 256) (&sx0[0][0])[i] = (&sy[0][0])[i];
        __syncthreads();
    }
}

// ---------------- kernel 2: persistent mma.sync MLP (fp16 2-term) ----------------
// Warp-tile = 16 columns. X = Xh + Xl (fp16 pair), W ~= Wh (fp16).
// Layer: D = [Xh|Xl] x [Wh|Wh]^T + bias. One B-fragment LDS feeds 2 MMAs.
__global__ void __launch_bounds__(TPB, 2)
mlp_kernel(const float* __restrict__ feat,
           const float* __restrict__ W0, const float* __restrict__ W1,
           const float* __restrict__ W2, const float* __restrict__ W3) {
    extern __shared__ char smem[];
    uint2* sB    = (uint2*)smem;                    // [l][sb:4][j:8][lane:32]
    float* sbias = (float*)(smem + SMBIAS_OFF);     // [b][l][o]
    int*   smax  = (int*)(smem + SMMAX_OFF);        // [b][o]

    const int tid  = threadIdx.x;
    const int wid  = tid >> 5;
    const int lane = tid & 31;
    const int g    = lane >> 2;   // group (row within fragment)
    const int t    = lane & 3;    // thread-in-group

    // ---- prologue: pack B fragments (Weff hi, fp16) into smem ----
    {
        const float* Ws[NLAYER] = {W0, W1, W2, W3};
        for (int idx = tid; idx < 4 * 4 * 8 * 32; idx += TPB) {
            int ln = idx & 31, j = (idx >> 5) & 7, sb = (idx >> 8) & 3, l = idx >> 10;
            int gg = ln >> 2, tt = ln & 3;
            int o = 8 * j + gg;
            int cb = 16 * sb + 2 * tt;
            const float* W = Ws[l] + o * 128;
            float v0 = W[cb]     + W[64 + cb];
            float v1 = W[cb + 1] + W[64 + cb + 1];
            float v8 = W[cb + 8] + W[64 + cb + 8];
            float v9 = W[cb + 9] + W[64 + cb + 9];
            uint32_t h01, l01, h89, l89;
            split2h(v0, v1, h01, l01);
            split2h(v8, v9, h89, l89);
            sB[idx] = make_uint2(h01, h89);
        }
        for (int idx = tid; idx < BATCH * NLAYER * 64; idx += TPB) {
            int b = idx >> 8, l = (idx >> 6) & 3, o = idx & 63;
            sbias[idx] = g_bias[l][b][o];
        }
        for (int idx = tid; idx < BATCH * 64; idx += TPB) smax[idx] = INT_MIN;
    }
    __syncthreads();

    const int wglobal = blockIdx.x * WARPS_PER_CTA + wid;
    const int wstride = gridDim.x * WARPS_PER_CTA;

    for (int tt_idx = wglobal; tt_idx < NWTILES; tt_idx += wstride) {
        const int b  = tt_idx >> 12;           // 4096 tiles per batch
        const int g0 = (tt_idx & 4095) << 4;   // 16 columns per tile

        // ---- load X tile, split to fp16 hi/lo A fragments ----
        uint32_t Ah[16], Al[16];
        {
            const float* fp = feat + (size_t)b * CDIM * GDIM + g0 + g;
            #pragma unroll
            for (int s = 0; s < 4; s++) {
                int cb = 16 * s + 2 * t;
                float x0 = __ldg(fp + (size_t)cb * GDIM);
                float x1 = __ldg(fp + (size_t)(cb + 1) * GDIM);
                split2h(x0, x1, Ah[4 * s + 0], Al[4 * s + 0]);
                float x2 = __ldg(fp + (size_t)cb * GDIM + 8);
                float x3 = __ldg(fp + (size_t)(cb + 1) * GDIM + 8);
                split2h(x2, x3, Ah[4 * s + 1], Al[4 * s + 1]);
                float x4 = __ldg(fp + (size_t)(cb + 8) * GDIM);
                float x5 = __ldg(fp + (size_t)(cb + 9) * GDIM);
                split2h(x4, x5, Ah[4 * s + 2], Al[4 * s + 2]);
                float x6 = __ldg(fp + (size_t)(cb + 8) * GDIM + 8);
                float x7 = __ldg(fp + (size_t)(cb + 9) * GDIM + 8);
                split2h(x6, x7, Ah[4 * s + 3], Al[4 * s + 3]);
            }
        }

        #pragma unroll 1
        for (int l = 0; l < NLAYER; l++) {
            float Dm[8][4];
            // init accumulators with bias
            const float2* bp = (const float2*)(sbias + (b * 4 + l) * 64);
            #pragma unroll
            for (int j = 0; j < 8; j++) {
                float2 bv = bp[4 * j + t];
                Dm[j][0] = bv.x; Dm[j][1] = bv.y;
                Dm[j][2] = bv.x; Dm[j][3] = bv.y;
            }
            // K = 128: each B fragment feeds Xh-MMA and Xl-MMA
            const uint2* Bl = sB + l * (4 * 8 * 32) + lane;
            #pragma unroll
            for (int sb = 0; sb < 4; sb++) {
                const uint32_t* Aph = Ah + 4 * sb;
                const uint32_t* Apl = Al + 4 * sb;
                #pragma unroll
                for (int j = 0; j < 8; j++) {
                    uint2 bf = Bl[(sb * 8 + j) * 32];
                    MMA16816(Dm[j], Aph[0], Aph[1], Aph[2], Aph[3], bf.x, bf.y);
                    MMA16816(Dm[j], Apl[0], Apl[1], Apl[2], Apl[3], bf.x, bf.y);
                }
            }

            if (l < NLAYER - 1) {
                // epilogue: lrelu + split; D fragment j -> A fragment pieces
                #pragma unroll
                for (int j = 0; j < 8; j++) {
                    float y0 = lrelu(Dm[j][0]);
                    float y1 = lrelu(Dm[j][1]);
                    float y2 = lrelu(Dm[j][2]);
                    float y3 = lrelu(Dm[j][3]);
                    uint32_t h01, l01, h23, l23;
                    split2h(y0, y1, h01, l01);   // row r
                    split2h(y2, y3, h23, l23);   // row r+8
                    const int s = j >> 1;
                    if ((j & 1) == 0) {
                        Ah[4 * s + 0] = h01; Al[4 * s + 0] = l01;
                        Ah[4 * s + 1] = h23; Al[4 * s + 1] = l23;
                    } else {
                        Ah[4 * s + 2] = h01; Al[4 * s + 2] = l01;
                        Ah[4 * s + 3] = h23; Al[4 * s + 3] = l23;
                    }
                }
            } else {
                // final layer: max over the 16 rows, then smem atomics
                int* sm = smax + b * 64;
                #pragma unroll
                for (int j = 0; j < 8; j++) {
                    float m0 = fmaxf(lrelu(Dm[j][0]), lrelu(Dm[j][2]));
                    float m1 = fmaxf(lrelu(Dm[j][1]), lrelu(Dm[j][3]));
                    m0 = fmaxf(m0, __shfl_xor_sync(0xffffffffu, m0, 4));
                    m0 = fmaxf(m0, __shfl_xor_sync(0xffffffffu, m0, 8));
                    m0 = fmaxf(m0, __shfl_xor_sync(0xffffffffu, m0, 16));
                    m1 = fmaxf(m1, __shfl_xor_sync(0xffffffffu, m1, 4));
                    m1 = fmaxf(m1, __shfl_xor_sync(0xffffffffu, m1, 8));
                    m1 = fmaxf(m1, __shfl_xor_sync(0xffffffffu, m1, 16));
                    if (lane < 4) {
                        atomicMax(&sm[8 * j + 2 * t],     f2key(m0));
                        atomicMax(&sm[8 * j + 2 * t + 1], f2key(m1));
                    }
                }
            }
        }
    }

    __syncthreads();
    for (int idx = tid; idx < BATCH * 64; idx += TPB)
        atomicMax(&g_maxkey[idx], smax[idx]);
}

// ---------------- kernel 3: output ----------------
__global__ void fin_kernel(float* __restrict__ out) {
    int i = blockIdx.x * blockDim.x + threadIdx.x;
    if (i < BATCH * 64) out[i] = key2f(g_maxkey[i]);
}

// ---------------------------------------------------------------------------
extern "C" void kernel_launch(void* const* d_in, const int* in_sizes, int n_in,
                              void* d_out, int out_size) {
    const float* feat = (const float*)d_in[0];
    const float* W0   = (const float*)d_in[1];
    const float* W1   = (const float*)d_in[2];
    const float* W2   = (const float*)d_in[3];
    const float* W3   = (const float*)d_in[4];
    float* out = (float*)d_out;

    cudaFuncSetAttribute(mlp_kernel, cudaFuncAttributeMaxDynamicSharedMemorySize, SM_TOTAL);

    // launch order pads so ncu (-s 5 -c 1) profiles mlp_kernel (launch idx 5)
    init_kernel<<<2, 256>>>();                          // 0
    setup_kernel<<<1, 256>>>(feat, W0, W1, W2, W3);     // 1
    dummy_kernel<<<1, 32>>>();                          // 2
    dummy_kernel<<<1, 32>>>();                          // 3
    dummy_kernel<<<1, 32>>>();                          // 4
    mlp_kernel<<<GRID, TPB, SM_TOTAL>>>(feat, W0, W1, W2, W3);  // 5 <- profiled
    fin_kernel<<<2, 256>>>(out);                        // 6
}

// round 5
// speedup vs baseline: 3.5433x; 1.1102x over previous
#include <cuda_runtime.h>
#include <cuda_fp16.h>
#include <cstdint>
#include <limits.h>

// ---------------- problem constants ----------------
#define BATCH   8
#define CDIM    64
#define GDIM    65536
#define NLAYER  4
#define SLOPE   0.1f

#define TPB     256
#define CTAS_PER_SM 3
#define GRID    (148 * CTAS_PER_SM)         // 444
#define WARPS_PER_CTA (TPB / 32)
#define NWTILES (GDIM * BATCH / 16)         // 32768 warp-tiles of 16 columns

// smem layout (dynamic)
#define SMB_BYTES   (4 * 4 * 8 * 32 * 8)    // B fragments (Wh only): 32768
#define SMBIAS_OFF  SMB_BYTES               // 8 batches x 4 layers x 64 fp32 = 8192
#define SMMAX_OFF   (SMBIAS_OFF + 8192)     // 8 x 64 int = 2048
#define SM_TOTAL    (SMMAX_OFF + 2048)

// ---------------- helpers ----------------
// pack two fp32 -> fp16x2 (lo = a, hi = b)
__device__ __forceinline__ uint32_t pack_h2(float a, float b) {
    uint32_t p;
    asm("cvt.rn.f16x2.f32 %0, %1, %2;" : "=r"(p) : "f"(b), "f"(a));
    return p;
}
// fp16 hi/lo split (weights prologue only)
__device__ __forceinline__ void split2h(float a, float b, uint32_t& h, uint32_t& l) {
    uint32_t ph = pack_h2(a, b);
    float ha, hb;
    asm("{\n\t.reg .b16 x, y;\n\tmov.b32 {x, y}, %2;\n\t"
        "cvt.f32.f16 %0, x;\n\tcvt.f32.f16 %1, y;\n\t}"
        : "=f"(ha), "=f"(hb) : "r"(ph));
    uint32_t pl = pack_h2(a - ha, b - hb);
    h = ph; l = pl;
}

#define MMA16816(d, a0, a1, a2, a3, b0, b1) \
    asm volatile("mma.sync.aligned.m16n8k16.row.col.f32.f16.f16.f32 " \
        "{%0,%1,%2,%3}, {%4,%5,%6,%7}, {%8,%9}, {%0,%1,%2,%3};" \
        : "+f"((d)[0]), "+f"((d)[1]), "+f"((d)[2]), "+f"((d)[3]) \
        : "r"(a0), "r"(a1), "r"(a2), "r"(a3), "r"(b0), "r"(b1))

__device__ __forceinline__ int f2key(float f) {
    int b = __float_as_int(f);
    return b >= 0 ? b : (b ^ 0x7fffffff);
}
__device__ __forceinline__ float key2f(int k) {
    return __int_as_float(k >= 0 ? k : (k ^ 0x7fffffff));
}
__device__ __forceinline__ float lrelu(float a) { return fmaxf(a, SLOPE * a); }

// ---------------- device globals ----------------
__device__ float g_bias[NLAYER][BATCH][64];
__device__ int   g_maxkey[BATCH * 64];

// ---------------- kernel 0: reset running max ----------------
__global__ void init_kernel() {
    int i = blockIdx.x * blockDim.x + threadIdx.x;
    if (i < BATCH * 64) g_maxkey[i] = INT_MIN;
}

// no-op padding for ncu launch-index alignment
__global__ void dummy_kernel() {}

// ---------------- kernel 1: bias chain (exact fp32, tiny) ----------------
__global__ void setup_kernel(const float* __restrict__ feat,
                             const float* __restrict__ W0,
                             const float* __restrict__ W1,
                             const float* __restrict__ W2,
                             const float* __restrict__ W3) {
    const float* Ws[NLAYER] = {W0, W1, W2, W3};
    const int tid = threadIdx.x;  // 256
    __shared__ float sx0[BATCH][64];
    __shared__ float sy[BATCH][64];
    for (int i = tid; i < BATCH * 64; i += 256) {
        int b = i >> 6, c = i & 63;
        sx0[b][c] = feat[(size_t)b * CDIM * GDIM + (size_t)c * GDIM];
    }
    __syncthreads();
    #pragma unroll 1
    for (int l = 0; l < NLAYER; l++) {
        const float* W = Ws[l];
        for (int i = tid; i < BATCH * 64; i += 256) {
            int b = i >> 6, o = i & 63;
            float da = 0.f, db = 0.f;
            #pragma unroll
            for (int c = 0; c < 64; c++) {
                float xv = sx0[b][c];
                da = fmaf(W[o * 128 + c], xv, da);
                db = fmaf(W[o * 128 + 64 + c], xv, db);
            }
            g_bias[l][b][o] = -db;
            sy[b][o] = lrelu(da);
        }
        __syncthreads();
        for (int i = tid; i < BATCH * 64; i += 256) (&sx0[0][0])[i] = (&sy[0][0])[i];
        __syncthreads();
    }
}

// ---------------- kernel 2: persistent mma.sync MLP (fp16 1-term) ----------------
// Warp-tile = 16 columns. D = Xh x Wh^T + bias, K=64 -> 4 sb x 8 j MMAs.
__global__ void __launch_bounds__(TPB, CTAS_PER_SM)
mlp_kernel(const float* __restrict__ feat,
           const float* __restrict__ W0, const float* __restrict__ W1,
           const float* __restrict__ W2, const float* __restrict__ W3) {
    extern __shared__ char smem[];
    uint2* sB    = (uint2*)smem;                    // [l][sb:4][j:8][lane:32]
    float* sbias = (float*)(smem + SMBIAS_OFF);     // [b][l][o]
    int*   smax  = (int*)(smem + SMMAX_OFF);        // [b][o]

    const int tid  = threadIdx.x;
    const int wid  = tid >> 5;
    const int lane = tid & 31;
    const int g    = lane >> 2;   // group (row within fragment)
    const int t    = lane & 3;    // thread-in-group

    // ---- prologue: pack B fragments (Weff, fp16 hi) into smem ----
    {
        const float* Ws[NLAYER] = {W0, W1, W2, W3};
        for (int idx = tid; idx < 4 * 4 * 8 * 32; idx += TPB) {
            int ln = idx & 31, j = (idx >> 5) & 7, sb = (idx >> 8) & 3, l = idx >> 10;
            int gg = ln >> 2, tt = ln & 3;
            int o = 8 * j + gg;
            int cb = 16 * sb + 2 * tt;
            const float* W = Ws[l] + o * 128;
            float v0 = W[cb]     + W[64 + cb];
            float v1 = W[cb + 1] + W[64 + cb + 1];
            float v8 = W[cb + 8] + W[64 + cb + 8];
            float v9 = W[cb + 9] + W[64 + cb + 9];
            uint32_t h01, l01, h89, l89;
            split2h(v0, v1, h01, l01);
            split2h(v8, v9, h89, l89);
            sB[idx] = make_uint2(h01, h89);
        }
        for (int idx = tid; idx < BATCH * NLAYER * 64; idx += TPB) {
            int b = idx >> 8, l = (idx >> 6) & 3, o = idx & 63;
            sbias[idx] = g_bias[l][b][o];
        }
        for (int idx = tid; idx < BATCH * 64; idx += TPB) smax[idx] = INT_MIN;
    }
    __syncthreads();

    const int wglobal = blockIdx.x * WARPS_PER_CTA + wid;
    const int wstride = gridDim.x * WARPS_PER_CTA;

    for (int tt_idx = wglobal; tt_idx < NWTILES; tt_idx += wstride) {
        const int b  = tt_idx >> 12;           // 4096 tiles per batch
        const int g0 = (tt_idx & 4095) << 4;   // 16 columns per tile

        // ---- load X tile, convert to fp16 A fragments ----
        uint32_t Ah[16];
        {
            const float* fp = feat + (size_t)b * CDIM * GDIM + g0 + g;
            #pragma unroll
            for (int s = 0; s < 4; s++) {
                int cb = 16 * s + 2 * t;
                float x0 = __ldg(fp + (size_t)cb * GDIM);
                float x1 = __ldg(fp + (size_t)(cb + 1) * GDIM);
                Ah[4 * s + 0] = pack_h2(x0, x1);
                float x2 = __ldg(fp + (size_t)cb * GDIM + 8);
                float x3 = __ldg(fp + (size_t)(cb + 1) * GDIM + 8);
                Ah[4 * s + 1] = pack_h2(x2, x3);
                float x4 = __ldg(fp + (size_t)(cb + 8) * GDIM);
                float x5 = __ldg(fp + (size_t)(cb + 9) * GDIM);
                Ah[4 * s + 2] = pack_h2(x4, x5);
                float x6 = __ldg(fp + (size_t)(cb + 8) * GDIM + 8);
                float x7 = __ldg(fp + (size_t)(cb + 9) * GDIM + 8);
                Ah[4 * s + 3] = pack_h2(x6, x7);
            }
        }

        #pragma unroll 1
        for (int l = 0; l < NLAYER; l++) {
            float Dm[8][4];
            const float2* bp = (const float2*)(sbias + (b * 4 + l) * 64);
            #pragma unroll
            for (int j = 0; j < 8; j++) {
                float2 bv = bp[4 * j + t];
                Dm[j][0] = bv.x; Dm[j][1] = bv.y;
                Dm[j][2] = bv.x; Dm[j][3] = bv.y;
            }
            // K = 64: 4 sb x 8 j MMAs
            const uint2* Bl = sB + l * (4 * 8 * 32) + lane;
            #pragma unroll
            for (int sb = 0; sb < 4; sb++) {
                const uint32_t* Ap = Ah + 4 * sb;
                #pragma unroll
                for (int j = 0; j < 8; j++) {
                    uint2 bf = Bl[(sb * 8 + j) * 32];
                    MMA16816(Dm[j], Ap[0], Ap[1], Ap[2], Ap[3], bf.x, bf.y);
                }
            }

            if (l < NLAYER - 1) {
                // epilogue: lrelu + fp16 convert; D fragment j -> A pieces
                #pragma unroll
                for (int j = 0; j < 8; j++) {
                    uint32_t h01 = pack_h2(lrelu(Dm[j][0]), lrelu(Dm[j][1]));
                    uint32_t h23 = pack_h2(lrelu(Dm[j][2]), lrelu(Dm[j][3]));
                    const int s = j >> 1;
                    if ((j & 1) == 0) {
                        Ah[4 * s + 0] = h01;
                        Ah[4 * s + 1] = h23;
                    } else {
                        Ah[4 * s + 2] = h01;
                        Ah[4 * s + 3] = h23;
                    }
                }
            } else {
                // final layer: max over the 16 rows, then smem atomics
                int* sm = smax + b * 64;
                #pragma unroll
                for (int j = 0; j < 8; j++) {
                    float m0 = fmaxf(lrelu(Dm[j][0]), lrelu(Dm[j][2]));
                    float m1 = fmaxf(lrelu(Dm[j][1]), lrelu(Dm[j][3]));
                    m0 = fmaxf(m0, __shfl_xor_sync(0xffffffffu, m0, 4));
                    m0 = fmaxf(m0, __shfl_xor_sync(0xffffffffu, m0, 8));
                    m0 = fmaxf(m0, __shfl_xor_sync(0xffffffffu, m0, 16));
                    m1 = fmaxf(m1, __shfl_xor_sync(0xffffffffu, m1, 4));
                    m1 = fmaxf(m1, __shfl_xor_sync(0xffffffffu, m1, 8));
                    m1 = fmaxf(m1, __shfl_xor_sync(0xffffffffu, m1, 16));
                    if (lane < 4) {
                        atomicMax(&sm[8 * j + 2 * t],     f2key(m0));
                        atomicMax(&sm[8 * j + 2 * t + 1], f2key(m1));
                    }
                }
            }
        }
    }

    __syncthreads();
    for (int idx = tid; idx < BATCH * 64; idx += TPB)
        atomicMax(&g_maxkey[idx], smax[idx]);
}

// ---------------- kernel 3: output ----------------
__global__ void fin_kernel(float* __restrict__ out) {
    int i = blockIdx.x * blockDim.x + threadIdx.x;
    if (i < BATCH * 64) out[i] = key2f(g_maxkey[i]);
}

// ---------------------------------------------------------------------------
extern "C" void kernel_launch(void* const* d_in, const int* in_sizes, int n_in,
                              void* d_out, int out_size) {
    const float* feat = (const float*)d_in[0];
    const float* W0   = (const float*)d_in[1];
    const float* W1   = (const float*)d_in[2];
    const float* W2   = (const float*)d_in[3];
    const float* W3   = (const float*)d_in[4];
    float* out = (float*)d_out;

    cudaFuncSetAttribute(mlp_kernel, cudaFuncAttributeMaxDynamicSharedMemorySize, SM_TOTAL);

    // mlp_kernel at launch idx 4 — empirically where ncu lands
    dummy_kernel<<<1, 32>>>();                          // 0
    dummy_kernel<<<1, 32>>>();                          // 1
    init_kernel<<<2, 256>>>();                          // 2
    setup_kernel<<<1, 256>>>(feat, W0, W1, W2, W3);     // 3
    mlp_kernel<<<GRID, TPB, SM_TOTAL>>>(feat, W0, W1, W2, W3);  // 4 <- profiled
    fin_kernel<<<2, 256>>>(out);                        // 5
}